// round 14
// baseline (speedup 1.0000x reference)
#include <cuda_runtime.h>
#include <cuda_fp16.h>
#include <cstdint>

#define BATCH   2
#define SEQ     4096
#define DIMM    1024
#define HEADS   16
#define DHEAD   64
#define ROWS    (BATCH*SEQ)
#define DINNER  (HEADS*DHEAD)

__device__ __half g_xn_h[ROWS * DIMM];
__device__ __half g_qh[BATCH * HEADS * SEQ * DHEAD];
__device__ __half g_kh[BATCH * HEADS * SEQ * DHEAD];
__device__ __half g_vh[BATCH * HEADS * SEQ * DHEAD];
__device__ float  g_gate[ROWS * HEADS];
__device__ __half g_attn_h[ROWS * DINNER];
__device__ __half g_wqkv_h[3 * DINNER * DIMM];
__device__ __half g_wout_h[DIMM * DINNER];

__device__ __forceinline__ uint32_t smem_u32(const void* p) {
    uint32_t a;
    asm("{ .reg .u64 t; cvta.to.shared.u64 t, %1; cvt.u32.u64 %0, t; }" : "=r"(a) : "l"(p));
    return a;
}
__device__ __forceinline__ void cp16(uint32_t s, const void* g) {
    asm volatile("cp.async.cg.shared.global [%0], [%1], 16;" :: "r"(s), "l"(g));
}
#define CP_COMMIT() asm volatile("cp.async.commit_group;" ::: "memory")
#define CP_WAIT1()  asm volatile("cp.async.wait_group 1;" ::: "memory")
#define CP_WAIT0()  asm volatile("cp.async.wait_group 0;" ::: "memory")

__device__ __forceinline__ void ldsm4(uint32_t& r0, uint32_t& r1, uint32_t& r2, uint32_t& r3, uint32_t a) {
    asm volatile("ldmatrix.sync.aligned.m8n8.x4.shared.b16 {%0,%1,%2,%3}, [%4];"
                 : "=r"(r0), "=r"(r1), "=r"(r2), "=r"(r3) : "r"(a));
}
__device__ __forceinline__ void ldsm4t(uint32_t& r0, uint32_t& r1, uint32_t& r2, uint32_t& r3, uint32_t a) {
    asm volatile("ldmatrix.sync.aligned.m8n8.x4.trans.shared.b16 {%0,%1,%2,%3}, [%4];"
                 : "=r"(r0), "=r"(r1), "=r"(r2), "=r"(r3) : "r"(a));
}
__device__ __forceinline__ void mma16816(float* d, const uint32_t* a, const uint32_t* b) {
    asm volatile("mma.sync.aligned.m16n8k16.row.col.f32.f16.f16.f32 "
                 "{%0,%1,%2,%3}, {%4,%5,%6,%7}, {%8,%9}, {%0,%1,%2,%3};"
                 : "+f"(d[0]), "+f"(d[1]), "+f"(d[2]), "+f"(d[3])
                 : "r"(a[0]), "r"(a[1]), "r"(a[2]), "r"(a[3]), "r"(b[0]), "r"(b[1]));
}
__device__ __forceinline__ uint32_t packh2(float a, float b) {
    __half2 h = __floats2half2_rn(a, b);
    return *(uint32_t*)&h;
}

// RMSNorm -> fp16, fused gates GEMV with coalesced Wg access
__global__ void rms_kernel(const float* __restrict__ x, const float* __restrict__ gamma,
                           const float* __restrict__ Wg, const float* __restrict__ bg) {
    int row = blockIdx.x;
    int t = threadIdx.x;
    __shared__ __half xs[DIMM];
    __shared__ float red[8];
    __shared__ float snorm;
    __shared__ float partial[8][16];
    const float4* xr = (const float4*)(x + (size_t)row * DIMM);
    float4 a = xr[t];
    float ss = a.x*a.x + a.y*a.y + a.z*a.z + a.w*a.w;
    #pragma unroll
    for (int o = 16; o > 0; o >>= 1) ss += __shfl_down_sync(0xffffffffu, ss, o);
    if ((t & 31) == 0) red[t >> 5] = ss;
    __syncthreads();
    if (t == 0) {
        float s = 0.f;
        #pragma unroll
        for (int i = 0; i < 8; i++) s += red[i];
        snorm = 32.0f / fmaxf(sqrtf(s), 1e-12f);
    }
    __syncthreads();
    float sc = snorm;
    float4 g = ((const float4*)gamma)[t];
    __half2 h01 = __floats2half2_rn(a.x * sc * g.x, a.y * sc * g.y);
    __half2 h23 = __floats2half2_rn(a.z * sc * g.z, a.w * sc * g.w);
    __half2* ph = (__half2*)(g_xn_h + (size_t)row * DIMM);
    ph[2*t]   = h01;
    ph[2*t+1] = h23;
    *(__half2*)&xs[4*t]   = h01;
    *(__half2*)&xs[4*t+2] = h23;
    __syncthreads();

    const int h = t & 15;
    const int jbase = t >> 4;
    float sum = 0.f;
    #pragma unroll 8
    for (int p = 0; p < 64; p++) {
        int j = jbase + 16 * p;
        sum += __half2float(xs[j]) * __ldg(&Wg[j * HEADS + h]);
    }
    sum += __shfl_down_sync(0xffffffffu, sum, 16);
    int wrp = t >> 5, lane = t & 31;
    if (lane < 16) partial[wrp][lane] = sum;
    __syncthreads();
    if (t < 16) {
        float s = 0.f;
        #pragma unroll
        for (int wq = 0; wq < 8; wq++) s += partial[wq][t];
        float v = s + bg[t];
        g_gate[row * HEADS + t] = 1.f / (1.f + __expf(-v));
    }
}

// merged transpose of both weights -> fp16 [N,K]
__global__ void transpose2_h(const float* __restrict__ W0, __half* __restrict__ o0,
                             const float* __restrict__ W1, __half* __restrict__ o1) {
    const float* W; __half* out; int N;
    if (blockIdx.z == 0) { W = W0; out = o0; N = 3 * DINNER; }
    else                 { W = W1; out = o1; N = DIMM; if ((int)blockIdx.x >= N / 32) return; }
    __shared__ float t[32][33];
    int tx = threadIdx.x, ty = threadIdx.y;
    int x = blockIdx.x * 32 + tx;
    int y0 = blockIdx.y * 32;
    #pragma unroll
    for (int r = ty; r < 32; r += 8)
        t[r][tx] = W[(size_t)(y0 + r) * N + x];
    __syncthreads();
    #pragma unroll
    for (int r = 0; r < 4; r++) {
        int a = ty + r * 8;
        out[(size_t)(blockIdx.x * 32 + a) * DIMM + y0 + tx] = __float2half_rn(t[tx][a]);
    }
}

// fp16 mma.sync GEMM 128x128 CTA tile, K-block 64, 3-stage cp.async pipeline
#define KBLK        64
#define PITCHB      144
#define MAT_BYTES   (128 * PITCHB)
#define STG_BYTES   (2 * MAT_BYTES)
#define NSTAGE      3
#define GSMEM_TOTAL (NSTAGE * STG_BYTES)

template<int MODE>
__global__ __launch_bounds__(256) void mma_gemm_kernel(
    const __half* __restrict__ A, const __half* __restrict__ B,
    float* __restrict__ C)
{
    extern __shared__ char smem[];
    const uint32_t sb = smem_u32(smem);
    const int tid = threadIdx.x;
    const int lane = tid & 31, wid = tid >> 5;
    const int wm = wid >> 2, wn = wid & 3;
    const int bx = blockIdx.x, by = blockIdx.y;

    const __half* gmat[2] = {A + (size_t)(by * 128) * DIMM, B + (size_t)(bx * 128) * DIMM};

    int ld_mat[8], ld_row[8], ld_ch[8];
    #pragma unroll
    for (int i = 0; i < 8; i++) {
        int idx = tid + i * 256;
        ld_mat[i] = idx >> 10;
        int rem = idx & 1023;
        ld_row[i] = rem >> 3;
        ld_ch[i]  = rem & 7;
    }

    float acc[4][4][4];
    #pragma unroll
    for (int mt = 0; mt < 4; mt++)
        #pragma unroll
        for (int nt = 0; nt < 4; nt++)
            #pragma unroll
            for (int r = 0; r < 4; r++) acc[mt][nt][r] = 0.f;

    const int quad = lane >> 3, l7 = lane & 7;
    const int a_row = (quad & 1) * 8 + l7;
    const int a_ch  = quad >> 1;
    const int b_row = (quad >> 1) * 8 + l7;
    const int b_ch  = quad & 1;

    auto load_stage = [&](int kb, int buf) {
        uint32_t s0 = sb + buf * STG_BYTES;
        #pragma unroll
        for (int i = 0; i < 8; i++) {
            const __half* g = gmat[ld_mat[i]] + (size_t)ld_row[i] * DIMM + kb * KBLK + ld_ch[i] * 8;
            cp16(s0 + ld_mat[i] * MAT_BYTES + ld_row[i] * PITCHB + ld_ch[i] * 16, g);
        }
        CP_COMMIT();
    };

    load_stage(0, 0);
    load_stage(1, 1);

    const int NKB = DIMM / KBLK;
    int buf = 0;
    for (int kb = 0; kb < NKB; kb++) {
        CP_WAIT1();
        __syncthreads();
        if (kb + 2 < NKB) {
            int nb = buf + 2; if (nb >= NSTAGE) nb -= NSTAGE;
            load_stage(kb + 2, nb);
        } else {
            CP_COMMIT();
        }
        const uint32_t s0 = sb + buf * STG_BYTES;
        const uint32_t sA = s0, sB = s0 + MAT_BYTES;

        #pragma unroll
        for (int ks = 0; ks < 4; ks++) {
            uint32_t ah[4][4], bh[2][4];
            #pragma unroll
            for (int mt = 0; mt < 4; mt++) {
                uint32_t off = (uint32_t)(wm * 64 + mt * 16 + a_row) * PITCHB + (ks * 2 + a_ch) * 16;
                ldsm4(ah[mt][0], ah[mt][1], ah[mt][2], ah[mt][3], sA + off);
            }
            #pragma unroll
            for (int np = 0; np < 2; np++) {
                uint32_t off = (uint32_t)(wn * 32 + np * 16 + b_row) * PITCHB + (ks * 2 + b_ch) * 16;
                ldsm4(bh[np][0], bh[np][1], bh[np][2], bh[np][3], sB + off);
            }
            #pragma unroll
            for (int mt = 0; mt < 4; mt++)
                #pragma unroll
                for (int np = 0; np < 2; np++)
                    #pragma unroll
                    for (int half = 0; half < 2; half++)
                        mma16816(acc[mt][np * 2 + half], ah[mt], &bh[np][half * 2]);
        }
        buf++; if (buf >= NSTAGE) buf = 0;
    }

    #pragma unroll
    for (int mt = 0; mt < 4; mt++) {
        #pragma unroll
        for (int nt = 0; nt < 4; nt++) {
            #pragma unroll
            for (int rp = 0; rp < 2; rp++) {
                int row = by * 128 + wm * 64 + mt * 16 + (lane >> 2) + rp * 8;
                int col = bx * 128 + wn * 32 + nt * 8 + (lane & 3) * 2;
                float v0 = acc[mt][nt][rp * 2], v1 = acc[mt][nt][rp * 2 + 1];
                if (MODE == 0) {
                    int which = col >> 10, h = (col >> 6) & 15, d0 = col & 63;
                    int bb = row >> 12, s = row & 4095;
                    __half* base = (which == 0) ? g_qh : (which == 1) ? g_kh : g_vh;
                    if (which == 0) { v0 *= 0.125f; v1 *= 0.125f; }
                    *(__half2*)&base[(((size_t)(bb * HEADS + h)) * SEQ + s) * DHEAD + d0] =
                        __floats2half2_rn(v0, v1);
                } else {
                    *(float2*)&C[(size_t)row * DIMM + col] = make_float2(v0, v1);
                }
            }
        }
    }
}

// tensor-core flash attention: 128-query CTA tile, 8 warps, 6 aligned 64-key chunks
__global__ __launch_bounds__(256) void attn_kernel() {
    const int h = blockIdx.y, bb = blockIdx.z;
    const int q0 = blockIdx.x * 128;
    const int tid = threadIdx.x, w = tid >> 5, l = tid & 31;

    __shared__ __half Qs[128 * 64];
    __shared__ __half KVs[2][2][64 * 64];
    const uint32_t qb = smem_u32(Qs);

    const size_t base = ((size_t)(bb * HEADS + h)) * SEQ * DHEAD;
    const int cstart = (q0 >= 256) ? 0 : ((256 - q0) >> 6);

    // Q load: 1024 16B chunks
    #pragma unroll
    for (int i = 0; i < 4; i++) {
        int idx = tid + i * 256;
        int row = idx >> 3, c16 = idx & 7;
        uint32_t bo = row * 128 + c16 * 16;
        cp16(qb + (bo ^ ((bo >> 3) & 0x70)), g_qh + base + (size_t)(q0 + row) * DHEAD + c16 * 8);
    }
    CP_COMMIT();

    // KV prologue: chunk cstart -> buf 0
    {
        const int ks = q0 - 256 + cstart * 64;
        const uint32_t kbb = smem_u32(&KVs[0][0][0]);
        const uint32_t vbb = smem_u32(&KVs[0][1][0]);
        #pragma unroll
        for (int i = 0; i < 2; i++) {
            int idx = tid + i * 256;
            int row = idx >> 3, c16 = idx & 7;
            uint32_t bo = row * 128 + c16 * 16;
            uint32_t sw = bo ^ ((bo >> 3) & 0x70);
            const size_t go = base + (size_t)(ks + row) * DHEAD + c16 * 8;
            cp16(kbb + sw, g_kh + go);
            cp16(vbb + sw, g_vh + go);
        }
        CP_COMMIT();
    }

    CP_WAIT1();
    __syncthreads();
    const int t8 = l >> 3, r8 = l & 7;
    uint32_t qf[4][4];
    #pragma unroll
    for (int kc = 0; kc < 4; kc++) {
        uint32_t bo = (uint32_t)(16 * w + (t8 & 1) * 8 + r8) * 128 + kc * 32 + (t8 >> 1) * 16;
        ldsm4(qf[kc][0], qf[kc][1], qf[kc][2], qf[kc][3], qb + (bo ^ ((bo >> 3) & 0x70)));
    }

    float o[8][4];
    #pragma unroll
    for (int nt = 0; nt < 8; nt++)
        #pragma unroll
        for (int e = 0; e < 4; e++) o[nt][e] = 0.f;
    float m0 = -1e30f, m1 = -1e30f, l0 = 0.f, l1 = 0.f;
    const int i0 = 16 * w + (l >> 2), i1 = i0 + 8;

    for (int c = cstart; c < 6; c++) {
        const int buf = (c - cstart) & 1;
        const uint32_t kbb = smem_u32(&KVs[buf][0][0]);
        const uint32_t vbb = smem_u32(&KVs[buf][1][0]);

        __syncthreads();
        if (c + 1 < 6) {
            const int ksn = q0 - 256 + (c + 1) * 64;
            const uint32_t kbn = smem_u32(&KVs[buf ^ 1][0][0]);
            const uint32_t vbn = smem_u32(&KVs[buf ^ 1][1][0]);
            #pragma unroll
            for (int i = 0; i < 2; i++) {
                int idx = tid + i * 256;
                int row = idx >> 3, c16 = idx & 7;
                uint32_t bo = row * 128 + c16 * 16;
                uint32_t sw = bo ^ ((bo >> 3) & 0x70);
                const size_t go = base + (size_t)(ksn + row) * DHEAD + c16 * 8;
                cp16(kbn + sw, g_kh + go);
                cp16(vbn + sw, g_vh + go);
            }
            CP_COMMIT();
            CP_WAIT1();
        } else {
            CP_WAIT0();
        }
        __syncthreads();

        // chunk 0 has zero valid keys for rows 64..127 (warps 4..7);
        // chunk 5 has zero valid keys for rows 0..63 (warps 0..3): skip compute.
        const bool active = !((c == 0 && w >= 4) || (c == 5 && w < 4));
        if (active) {
            float s[8][4];
            #pragma unroll
            for (int nt = 0; nt < 8; nt++)
                #pragma unroll
                for (int e = 0; e < 4; e++) s[nt][e] = 0.f;
            #pragma unroll
            for (int kc = 0; kc < 4; kc++) {
                #pragma unroll
                for (int g = 0; g < 4; g++) {
                    uint32_t t0, t1, t2, t3;
                    uint32_t bo = (uint32_t)(g * 16 + ((t8 >= 2) ? 8 : 0) + r8) * 128 + kc * 32 + (t8 & 1) * 16;
                    ldsm4(t0, t1, t2, t3, kbb + (bo ^ ((bo >> 3) & 0x70)));
                    uint32_t b0[2] = {t0, t1}, b1[2] = {t2, t3};
                    mma16816(s[2 * g],     qf[kc], b0);
                    mma16816(s[2 * g + 1], qf[kc], b1);
                }
            }

            // boundary masks: valid iff i-64c <= j <= i+256-64c
            if (c <= 1 || c >= 4) {
                #pragma unroll
                for (int nt = 0; nt < 8; nt++) {
                    #pragma unroll
                    for (int e = 0; e < 4; e++) {
                        int j = 8 * nt + 2 * (l & 3) + (e & 1);
                        int i = (e < 2) ? i0 : i1;
                        bool valid = (j >= i - 64 * c) && (j <= i + 256 - 64 * c);
                        if (!valid) s[nt][e] = -1e30f;
                    }
                }
            }

            float mr0 = -1e30f, mr1 = -1e30f;
            #pragma unroll
            for (int nt = 0; nt < 8; nt++) {
                mr0 = fmaxf(mr0, fmaxf(s[nt][0], s[nt][1]));
                mr1 = fmaxf(mr1, fmaxf(s[nt][2], s[nt][3]));
            }
            mr0 = fmaxf(mr0, __shfl_xor_sync(0xffffffffu, mr0, 1));
            mr0 = fmaxf(mr0, __shfl_xor_sync(0xffffffffu, mr0, 2));
            mr1 = fmaxf(mr1, __shfl_xor_sync(0xffffffffu, mr1, 1));
            mr1 = fmaxf(mr1, __shfl_xor_sync(0xffffffffu, mr1, 2));
            float mn0 = fmaxf(m0, mr0), mn1 = fmaxf(m1, mr1);
            float cr0 = __expf(m0 - mn0), cr1 = __expf(m1 - mn1);
            l0 *= cr0; l1 *= cr1;
            #pragma unroll
            for (int nt = 0; nt < 8; nt++) {
                o[nt][0] *= cr0; o[nt][1] *= cr0; o[nt][2] *= cr1; o[nt][3] *= cr1;
            }
            #pragma unroll
            for (int nt = 0; nt < 8; nt++) {
                s[nt][0] = __expf(s[nt][0] - mn0);
                s[nt][1] = __expf(s[nt][1] - mn0);
                s[nt][2] = __expf(s[nt][2] - mn1);
                s[nt][3] = __expf(s[nt][3] - mn1);
                l0 += s[nt][0] + s[nt][1];
                l1 += s[nt][2] + s[nt][3];
            }
            m0 = mn0; m1 = mn1;

            #pragma unroll
            for (int kc = 0; kc < 4; kc++) {
                uint32_t a[4];
                a[0] = packh2(s[2*kc][0],   s[2*kc][1]);
                a[1] = packh2(s[2*kc][2],   s[2*kc][3]);
                a[2] = packh2(s[2*kc+1][0], s[2*kc+1][1]);
                a[3] = packh2(s[2*kc+1][2], s[2*kc+1][3]);
                #pragma unroll
                for (int ng = 0; ng < 4; ng++) {
                    uint32_t t0, t1, t2, t3;
                    uint32_t bo = (uint32_t)(kc * 16 + ((t8 & 1) ? 8 : 0) + r8) * 128 + ng * 32 + ((t8 >= 2) ? 16 : 0);
                    ldsm4t(t0, t1, t2, t3, vbb + (bo ^ ((bo >> 3) & 0x70)));
                    uint32_t b0[2] = {t0, t1}, b1[2] = {t2, t3};
                    mma16816(o[2 * ng],     a, b0);
                    mma16816(o[2 * ng + 1], a, b1);
                }
            }
        }
    }

    l0 += __shfl_xor_sync(0xffffffffu, l0, 1);
    l0 += __shfl_xor_sync(0xffffffffu, l0, 2);
    l1 += __shfl_xor_sync(0xffffffffu, l1, 1);
    l1 += __shfl_xor_sync(0xffffffffu, l1, 2);

    int rg0 = bb * SEQ + q0 + i0, rg1 = rg0 + 8;
    float inv0 = g_gate[rg0 * HEADS + h] / l0;
    float inv1 = g_gate[rg1 * HEADS + h] / l1;
    #pragma unroll
    for (int nt = 0; nt < 8; nt++) {
        int d = 8 * nt + 2 * (l & 3);
        *(__half2*)&g_attn_h[(size_t)rg0 * DINNER + h * DHEAD + d] =
            __floats2half2_rn(o[nt][0] * inv0, o[nt][1] * inv0);
        *(__half2*)&g_attn_h[(size_t)rg1 * DINNER + h * DHEAD + d] =
            __floats2half2_rn(o[nt][2] * inv1, o[nt][3] * inv1);
    }
}

extern "C" void kernel_launch(void* const* d_in, const int* in_sizes, int n_in,
                              void* d_out, int out_size) {
    const float* x     = (const float*)d_in[0];
    const float* gamma = (const float*)d_in[1];
    const float* Wqkv  = (const float*)d_in[2];
    const float* Wg    = (const float*)d_in[3];
    const float* bg    = (const float*)d_in[4];
    const float* Wout  = (const float*)d_in[5];

    __half *xn_h, *wqkv_h, *wout_h, *attn_h;
    cudaGetSymbolAddress((void**)&xn_h,   g_xn_h);
    cudaGetSymbolAddress((void**)&wqkv_h, g_wqkv_h);
    cudaGetSymbolAddress((void**)&wout_h, g_wout_h);
    cudaGetSymbolAddress((void**)&attn_h, g_attn_h);

    cudaFuncSetAttribute(mma_gemm_kernel<0>, cudaFuncAttributeMaxDynamicSharedMemorySize, GSMEM_TOTAL);
    cudaFuncSetAttribute(mma_gemm_kernel<1>, cudaFuncAttributeMaxDynamicSharedMemorySize, GSMEM_TOTAL);

    transpose2_h<<<dim3(96, 32, 2), dim3(32, 8)>>>(Wqkv, wqkv_h, Wout, wout_h);
    rms_kernel<<<ROWS, 256>>>(x, gamma, Wg, bg);
    mma_gemm_kernel<0><<<dim3(3 * DINNER / 128, ROWS / 128), 256, GSMEM_TOTAL>>>(
        xn_h, wqkv_h, nullptr);
    attn_kernel<<<dim3(SEQ / 128, HEADS, BATCH), 256>>>();
    mma_gemm_kernel<1><<<dim3(DIMM / 128, ROWS / 128), 256, GSMEM_TOTAL>>>(
        attn_h, wout_h, (float*)d_out);
}

// round 15
// speedup vs baseline: 1.5855x; 1.5855x over previous
#include <cuda_runtime.h>
#include <cuda_fp16.h>
#include <cstdint>

#define BATCH   2
#define SEQ     4096
#define DIMM    1024
#define HEADS   16
#define DHEAD   64
#define ROWS    (BATCH*SEQ)
#define DINNER  (HEADS*DHEAD)

__device__ __half g_xn_h[ROWS * DIMM];
__device__ __half g_qh[BATCH * HEADS * SEQ * DHEAD];
__device__ __half g_kh[BATCH * HEADS * SEQ * DHEAD];
__device__ __half g_vh[BATCH * HEADS * SEQ * DHEAD];
__device__ float  g_gate[ROWS * HEADS];
__device__ __half g_attn_h[ROWS * DINNER];
__device__ __half g_wqkv_h[DIMM * 3 * DINNER];   // [K=1024, N=3072] native layout, fp16
__device__ __half g_wout_h[DIMM * DIMM];         // [K=1024, N=1024] native layout, fp16

__device__ __forceinline__ uint32_t smem_u32(const void* p) {
    uint32_t a;
    asm("{ .reg .u64 t; cvta.to.shared.u64 t, %1; cvt.u32.u64 %0, t; }" : "=r"(a) : "l"(p));
    return a;
}
__device__ __forceinline__ void cp16(uint32_t s, const void* g) {
    asm volatile("cp.async.cg.shared.global [%0], [%1], 16;" :: "r"(s), "l"(g));
}
#define CP_COMMIT() asm volatile("cp.async.commit_group;" ::: "memory")
#define CP_WAIT1()  asm volatile("cp.async.wait_group 1;" ::: "memory")
#define CP_WAIT0()  asm volatile("cp.async.wait_group 0;" ::: "memory")

__device__ __forceinline__ void ldsm4(uint32_t& r0, uint32_t& r1, uint32_t& r2, uint32_t& r3, uint32_t a) {
    asm volatile("ldmatrix.sync.aligned.m8n8.x4.shared.b16 {%0,%1,%2,%3}, [%4];"
                 : "=r"(r0), "=r"(r1), "=r"(r2), "=r"(r3) : "r"(a));
}
__device__ __forceinline__ void ldsm4t(uint32_t& r0, uint32_t& r1, uint32_t& r2, uint32_t& r3, uint32_t a) {
    asm volatile("ldmatrix.sync.aligned.m8n8.x4.trans.shared.b16 {%0,%1,%2,%3}, [%4];"
                 : "=r"(r0), "=r"(r1), "=r"(r2), "=r"(r3) : "r"(a));
}
__device__ __forceinline__ void mma16816(float* d, const uint32_t* a, const uint32_t* b) {
    asm volatile("mma.sync.aligned.m16n8k16.row.col.f32.f16.f16.f32 "
                 "{%0,%1,%2,%3}, {%4,%5,%6,%7}, {%8,%9}, {%0,%1,%2,%3};"
                 : "+f"(d[0]), "+f"(d[1]), "+f"(d[2]), "+f"(d[3])
                 : "r"(a[0]), "r"(a[1]), "r"(a[2]), "r"(a[3]), "r"(b[0]), "r"(b[1]));
}
__device__ __forceinline__ uint32_t packh2(float a, float b) {
    __half2 h = __floats2half2_rn(a, b);
    return *(uint32_t*)&h;
}

// RMSNorm -> fp16, fused gates GEMV with coalesced Wg access
__global__ void rms_kernel(const float* __restrict__ x, const float* __restrict__ gamma,
                           const float* __restrict__ Wg, const float* __restrict__ bg) {
    int row = blockIdx.x;
    int t = threadIdx.x;
    __shared__ __half xs[DIMM];
    __shared__ float red[8];
    __shared__ float snorm;
    __shared__ float partial[8][16];
    const float4* xr = (const float4*)(x + (size_t)row * DIMM);
    float4 a = xr[t];
    float ss = a.x*a.x + a.y*a.y + a.z*a.z + a.w*a.w;
    #pragma unroll
    for (int o = 16; o > 0; o >>= 1) ss += __shfl_down_sync(0xffffffffu, ss, o);
    if ((t & 31) == 0) red[t >> 5] = ss;
    __syncthreads();
    if (t == 0) {
        float s = 0.f;
        #pragma unroll
        for (int i = 0; i < 8; i++) s += red[i];
        snorm = 32.0f / fmaxf(sqrtf(s), 1e-12f);
    }
    __syncthreads();
    float sc = snorm;
    float4 g = ((const float4*)gamma)[t];
    __half2 h01 = __floats2half2_rn(a.x * sc * g.x, a.y * sc * g.y);
    __half2 h23 = __floats2half2_rn(a.z * sc * g.z, a.w * sc * g.w);
    __half2* ph = (__half2*)(g_xn_h + (size_t)row * DIMM);
    ph[2*t]   = h01;
    ph[2*t+1] = h23;
    *(__half2*)&xs[4*t]   = h01;
    *(__half2*)&xs[4*t+2] = h23;
    __syncthreads();

    const int h = t & 15;
    const int jbase = t >> 4;
    float sum = 0.f;
    #pragma unroll 8
    for (int p = 0; p < 64; p++) {
        int j = jbase + 16 * p;
        sum += __half2float(xs[j]) * __ldg(&Wg[j * HEADS + h]);
    }
    sum += __shfl_down_sync(0xffffffffu, sum, 16);
    int wrp = t >> 5, lane = t & 31;
    if (lane < 16) partial[wrp][lane] = sum;
    __syncthreads();
    if (t < 16) {
        float s = 0.f;
        #pragma unroll
        for (int wq = 0; wq < 8; wq++) s += partial[wq][t];
        float v = s + bg[t];
        g_gate[row * HEADS + t] = 1.f / (1.f + __expf(-v));
    }
}

// elementwise f32 -> fp16 convert of both weight matrices (native layout)
#define N0Q (DIMM * 3 * DINNER / 4)
#define N1Q (DIMM * DIMM / 4)
__global__ void convert_h(const float* __restrict__ W0, const float* __restrict__ W1) {
    for (int i = blockIdx.x * blockDim.x + threadIdx.x; i < N0Q + N1Q; i += gridDim.x * blockDim.x) {
        if (i < N0Q) {
            float4 v = ((const float4*)W0)[i];
            ((__half2*)g_wqkv_h)[2*i]   = __floats2half2_rn(v.x, v.y);
            ((__half2*)g_wqkv_h)[2*i+1] = __floats2half2_rn(v.z, v.w);
        } else {
            int j = i - N0Q;
            float4 v = ((const float4*)W1)[j];
            ((__half2*)g_wout_h)[2*j]   = __floats2half2_rn(v.x, v.y);
            ((__half2*)g_wout_h)[2*j+1] = __floats2half2_rn(v.z, v.w);
        }
    }
}

// fp16 mma.sync GEMM 128x128 CTA tile, K-block 64, 3-stage cp.async pipeline.
// A [M,1024] fp16 row-major; B [1024,NB] fp16 row-major (native weight layout),
// B fragments via ldmatrix.trans (same geometry as attn's V path).
#define KBLK        64
#define PITCH_A     144                      // 128B row + 16B pad
#define PITCH_B     272                      // 256B row + 16B pad (16x17 -> conflict-free)
#define MAT_A       (128 * PITCH_A)          // 18432
#define MAT_B       (64 * PITCH_B)           // 17408
#define STG_BYTES   (MAT_A + MAT_B)          // 35840
#define NSTAGE      3
#define GSMEM_TOTAL (NSTAGE * STG_BYTES)     // 107520

template<int MODE>
__global__ __launch_bounds__(256) void mma_gemm_kernel(
    const __half* __restrict__ A, const __half* __restrict__ Bw,
    float* __restrict__ C)
{
    constexpr int NB = (MODE == 0) ? 3 * DINNER : DIMM;
    extern __shared__ char smem[];
    const uint32_t sb = smem_u32(smem);
    const int tid = threadIdx.x;
    const int lane = tid & 31, wid = tid >> 5;
    const int wm = wid >> 2, wn = wid & 3;
    const int bx = blockIdx.x, by = blockIdx.y;

    const __half* gA = A + (size_t)(by * 128) * DIMM;
    const __half* gB = Bw + bx * 128;

    float acc[4][4][4];
    #pragma unroll
    for (int mt = 0; mt < 4; mt++)
        #pragma unroll
        for (int nt = 0; nt < 4; nt++)
            #pragma unroll
            for (int r = 0; r < 4; r++) acc[mt][nt][r] = 0.f;

    const int quad = lane >> 3, l7 = lane & 7;
    const int a_row = (quad & 1) * 8 + l7;
    const int a_ch  = quad >> 1;
    const int t8 = quad, r8 = l7;

    auto load_stage = [&](int kb, int buf) {
        uint32_t s0 = sb + buf * STG_BYTES;
        #pragma unroll
        for (int i = 0; i < 8; i++) {
            int idx = tid + i * 256;                 // 0..2047
            if (idx < 1024) {                        // A: 128 rows x 8 chunks
                int row = idx >> 3, ch = idx & 7;
                cp16(s0 + row * PITCH_A + ch * 16,
                     gA + (size_t)row * DIMM + kb * KBLK + ch * 8);
            } else {                                 // B: 64 rows x 16 chunks
                int j = idx - 1024;
                int row = j >> 4, ch = j & 15;
                cp16(s0 + MAT_A + row * PITCH_B + ch * 16,
                     gB + (size_t)(kb * KBLK + row) * NB + ch * 8);
            }
        }
        CP_COMMIT();
    };

    load_stage(0, 0);
    load_stage(1, 1);

    const int NKB = DIMM / KBLK;                     // 16
    int buf = 0;
    for (int kb = 0; kb < NKB; kb++) {
        CP_WAIT1();
        __syncthreads();
        if (kb + 2 < NKB) {
            int nb = buf + 2; if (nb >= NSTAGE) nb -= NSTAGE;
            load_stage(kb + 2, nb);
        } else {
            CP_COMMIT();
        }
        const uint32_t s0 = sb + buf * STG_BYTES;
        const uint32_t sA = s0, sB = s0 + MAT_A;

        #pragma unroll
        for (int ks = 0; ks < 4; ks++) {
            uint32_t ah[4][4];
            #pragma unroll
            for (int mt = 0; mt < 4; mt++) {
                uint32_t off = (uint32_t)(wm * 64 + mt * 16 + a_row) * PITCH_A + (ks * 2 + a_ch) * 16;
                ldsm4(ah[mt][0], ah[mt][1], ah[mt][2], ah[mt][3], sA + off);
            }
            #pragma unroll
            for (int np = 0; np < 2; np++) {
                uint32_t t0, t1, t2, t3;
                uint32_t off = (uint32_t)(ks * 16 + ((t8 & 1) ? 8 : 0) + r8) * PITCH_B
                             + (wn * 32 + np * 16) * 2 + ((t8 >= 2) ? 16 : 0);
                ldsm4t(t0, t1, t2, t3, sB + off);
                uint32_t b0[2] = {t0, t1}, b1[2] = {t2, t3};
                #pragma unroll
                for (int mt = 0; mt < 4; mt++) {
                    mma16816(acc[mt][np * 2 + 0], ah[mt], b0);
                    mma16816(acc[mt][np * 2 + 1], ah[mt], b1);
                }
            }
        }
        buf++; if (buf >= NSTAGE) buf = 0;
    }

    #pragma unroll
    for (int mt = 0; mt < 4; mt++) {
        #pragma unroll
        for (int nt = 0; nt < 4; nt++) {
            #pragma unroll
            for (int rp = 0; rp < 2; rp++) {
                int row = by * 128 + wm * 64 + mt * 16 + (lane >> 2) + rp * 8;
                int col = bx * 128 + wn * 32 + nt * 8 + (lane & 3) * 2;
                float v0 = acc[mt][nt][rp * 2], v1 = acc[mt][nt][rp * 2 + 1];
                if (MODE == 0) {
                    int which = col >> 10, h = (col >> 6) & 15, d0 = col & 63;
                    int bb = row >> 12, s = row & 4095;
                    __half* base = (which == 0) ? g_qh : (which == 1) ? g_kh : g_vh;
                    if (which == 0) { v0 *= 0.125f; v1 *= 0.125f; }
                    *(__half2*)&base[(((size_t)(bb * HEADS + h)) * SEQ + s) * DHEAD + d0] =
                        __floats2half2_rn(v0, v1);
                } else {
                    *(float2*)&C[(size_t)row * DIMM + col] = make_float2(v0, v1);
                }
            }
        }
    }
}

// tensor-core flash attention: 64-query CTA, 4 warps, double-buffered KV (round-13 proven)
__global__ __launch_bounds__(128) void attn_kernel() {
    const int tile = blockIdx.x, h = blockIdx.y, bb = blockIdx.z;
    const int q0 = tile * 64;
    const int tid = threadIdx.x, w = tid >> 5, l = tid & 31;

    __shared__ __half Qs[64 * 64];
    __shared__ __half KVs[2][2][64 * 64];
    const uint32_t qb = smem_u32(Qs);

    const size_t base = ((size_t)(bb * HEADS + h)) * SEQ * DHEAD;
    const int cstart = (q0 >= 256) ? 0 : ((256 - q0) >> 6);

    #pragma unroll
    for (int i = 0; i < 4; i++) {
        int idx = tid + i * 128;
        int row = idx >> 3, c16 = idx & 7;
        uint32_t bo = row * 128 + c16 * 16;
        cp16(qb + (bo ^ ((bo >> 3) & 0x70)), g_qh + base + (size_t)(q0 + row) * DHEAD + c16 * 8);
    }
    CP_COMMIT();

    {
        const int ks = q0 - 256 + cstart * 64;
        const uint32_t kbb = smem_u32(&KVs[0][0][0]);
        const uint32_t vbb = smem_u32(&KVs[0][1][0]);
        #pragma unroll
        for (int i = 0; i < 4; i++) {
            int idx = tid + i * 128;
            int row = idx >> 3, c16 = idx & 7;
            uint32_t bo = row * 128 + c16 * 16;
            uint32_t sw = bo ^ ((bo >> 3) & 0x70);
            const size_t go = base + (size_t)(ks + row) * DHEAD + c16 * 8;
            cp16(kbb + sw, g_kh + go);
            cp16(vbb + sw, g_vh + go);
        }
        CP_COMMIT();
    }

    CP_WAIT1();
    __syncthreads();
    const int t8 = l >> 3, r8 = l & 7;
    uint32_t qf[4][4];
    #pragma unroll
    for (int kc = 0; kc < 4; kc++) {
        uint32_t bo = (uint32_t)(16 * w + (t8 & 1) * 8 + r8) * 128 + kc * 32 + (t8 >> 1) * 16;
        ldsm4(qf[kc][0], qf[kc][1], qf[kc][2], qf[kc][3], qb + (bo ^ ((bo >> 3) & 0x70)));
    }

    float o[8][4];
    #pragma unroll
    for (int nt = 0; nt < 8; nt++)
        #pragma unroll
        for (int e = 0; e < 4; e++) o[nt][e] = 0.f;
    float m0 = -1e30f, m1 = -1e30f, l0 = 0.f, l1 = 0.f;
    const int i0 = 16 * w + (l >> 2), i1 = i0 + 8;

    for (int c = cstart; c < 5; c++) {
        const int buf = (c - cstart) & 1;
        const uint32_t kbb = smem_u32(&KVs[buf][0][0]);
        const uint32_t vbb = smem_u32(&KVs[buf][1][0]);

        __syncthreads();
        if (c + 1 < 5) {
            const int ksn = q0 - 256 + (c + 1) * 64;
            const uint32_t kbn = smem_u32(&KVs[buf ^ 1][0][0]);
            const uint32_t vbn = smem_u32(&KVs[buf ^ 1][1][0]);
            #pragma unroll
            for (int i = 0; i < 4; i++) {
                int idx = tid + i * 128;
                int row = idx >> 3, c16 = idx & 7;
                uint32_t bo = row * 128 + c16 * 16;
                uint32_t sw = bo ^ ((bo >> 3) & 0x70);
                const size_t go = base + (size_t)(ksn + row) * DHEAD + c16 * 8;
                cp16(kbn + sw, g_kh + go);
                cp16(vbn + sw, g_vh + go);
            }
            CP_COMMIT();
            CP_WAIT1();
        } else {
            CP_WAIT0();
        }
        __syncthreads();

        float s[8][4];
        #pragma unroll
        for (int nt = 0; nt < 8; nt++)
            #pragma unroll
            for (int e = 0; e < 4; e++) s[nt][e] = 0.f;
        #pragma unroll
        for (int kc = 0; kc < 4; kc++) {
            #pragma unroll
            for (int g = 0; g < 4; g++) {
                uint32_t t0, t1, t2, t3;
                uint32_t bo = (uint32_t)(g * 16 + ((t8 >= 2) ? 8 : 0) + r8) * 128 + kc * 32 + (t8 & 1) * 16;
                ldsm4(t0, t1, t2, t3, kbb + (bo ^ ((bo >> 3) & 0x70)));
                uint32_t b0[2] = {t0, t1}, b1[2] = {t2, t3};
                mma16816(s[2 * g],     qf[kc], b0);
                mma16816(s[2 * g + 1], qf[kc], b1);
            }
        }

        if (c == 0 || c == 4) {
            #pragma unroll
            for (int nt = 0; nt < 8; nt++) {
                #pragma unroll
                for (int e = 0; e < 4; e++) {
                    int j = 8 * nt + 2 * (l & 3) + (e & 1);
                    int i = (e < 2) ? i0 : i1;
                    bool valid = (c == 0) ? (j >= i) : (j <= i);
                    if (!valid) s[nt][e] = -1e30f;
                }
            }
        }

        float mr0 = -1e30f, mr1 = -1e30f;
        #pragma unroll
        for (int nt = 0; nt < 8; nt++) {
            mr0 = fmaxf(mr0, fmaxf(s[nt][0], s[nt][1]));
            mr1 = fmaxf(mr1, fmaxf(s[nt][2], s[nt][3]));
        }
        mr0 = fmaxf(mr0, __shfl_xor_sync(0xffffffffu, mr0, 1));
        mr0 = fmaxf(mr0, __shfl_xor_sync(0xffffffffu, mr0, 2));
        mr1 = fmaxf(mr1, __shfl_xor_sync(0xffffffffu, mr1, 1));
        mr1 = fmaxf(mr1, __shfl_xor_sync(0xffffffffu, mr1, 2));
        float mn0 = fmaxf(m0, mr0), mn1 = fmaxf(m1, mr1);
        float cr0 = __expf(m0 - mn0), cr1 = __expf(m1 - mn1);
        l0 *= cr0; l1 *= cr1;
        #pragma unroll
        for (int nt = 0; nt < 8; nt++) {
            o[nt][0] *= cr0; o[nt][1] *= cr0; o[nt][2] *= cr1; o[nt][3] *= cr1;
        }
        #pragma unroll
        for (int nt = 0; nt < 8; nt++) {
            s[nt][0] = __expf(s[nt][0] - mn0);
            s[nt][1] = __expf(s[nt][1] - mn0);
            s[nt][2] = __expf(s[nt][2] - mn1);
            s[nt][3] = __expf(s[nt][3] - mn1);
            l0 += s[nt][0] + s[nt][1];
            l1 += s[nt][2] + s[nt][3];
        }
        m0 = mn0; m1 = mn1;

        #pragma unroll
        for (int kc = 0; kc < 4; kc++) {
            uint32_t a[4];
            a[0] = packh2(s[2*kc][0],   s[2*kc][1]);
            a[1] = packh2(s[2*kc][2],   s[2*kc][3]);
            a[2] = packh2(s[2*kc+1][0], s[2*kc+1][1]);
            a[3] = packh2(s[2*kc+1][2], s[2*kc+1][3]);
            #pragma unroll
            for (int ng = 0; ng < 4; ng++) {
                uint32_t t0, t1, t2, t3;
                uint32_t bo = (uint32_t)(kc * 16 + ((t8 & 1) ? 8 : 0) + r8) * 128 + ng * 32 + ((t8 >= 2) ? 16 : 0);
                ldsm4t(t0, t1, t2, t3, vbb + (bo ^ ((bo >> 3) & 0x70)));
                uint32_t b0[2] = {t0, t1}, b1[2] = {t2, t3};
                mma16816(o[2 * ng],     a, b0);
                mma16816(o[2 * ng + 1], a, b1);
            }
        }
    }

    l0 += __shfl_xor_sync(0xffffffffu, l0, 1);
    l0 += __shfl_xor_sync(0xffffffffu, l0, 2);
    l1 += __shfl_xor_sync(0xffffffffu, l1, 1);
    l1 += __shfl_xor_sync(0xffffffffu, l1, 2);

    int rg0 = bb * SEQ + q0 + i0, rg1 = rg0 + 8;
    float inv0 = g_gate[rg0 * HEADS + h] / l0;
    float inv1 = g_gate[rg1 * HEADS + h] / l1;
    #pragma unroll
    for (int nt = 0; nt < 8; nt++) {
        int d = 8 * nt + 2 * (l & 3);
        *(__half2*)&g_attn_h[(size_t)rg0 * DINNER + h * DHEAD + d] =
            __floats2half2_rn(o[nt][0] * inv0, o[nt][1] * inv0);
        *(__half2*)&g_attn_h[(size_t)rg1 * DINNER + h * DHEAD + d] =
            __floats2half2_rn(o[nt][2] * inv1, o[nt][3] * inv1);
    }
}

extern "C" void kernel_launch(void* const* d_in, const int* in_sizes, int n_in,
                              void* d_out, int out_size) {
    const float* x     = (const float*)d_in[0];
    const float* gamma = (const float*)d_in[1];
    const float* Wqkv  = (const float*)d_in[2];
    const float* Wg    = (const float*)d_in[3];
    const float* bg    = (const float*)d_in[4];
    const float* Wout  = (const float*)d_in[5];

    __half *xn_h, *wqkv_h, *wout_h, *attn_h;
    cudaGetSymbolAddress((void**)&xn_h,   g_xn_h);
    cudaGetSymbolAddress((void**)&wqkv_h, g_wqkv_h);
    cudaGetSymbolAddress((void**)&wout_h, g_wout_h);
    cudaGetSymbolAddress((void**)&attn_h, g_attn_h);

    cudaFuncSetAttribute(mma_gemm_kernel<0>, cudaFuncAttributeMaxDynamicSharedMemorySize, GSMEM_TOTAL);
    cudaFuncSetAttribute(mma_gemm_kernel<1>, cudaFuncAttributeMaxDynamicSharedMemorySize, GSMEM_TOTAL);

    convert_h<<<592, 256>>>(Wqkv, Wout);
    rms_kernel<<<ROWS, 256>>>(x, gamma, Wg, bg);
    mma_gemm_kernel<0><<<dim3(3 * DINNER / 128, ROWS / 128), 256, GSMEM_TOTAL>>>(
        xn_h, wqkv_h, nullptr);
    attn_kernel<<<dim3(SEQ / 64, HEADS, BATCH), 128>>>();
    mma_gemm_kernel<1><<<dim3(DIMM / 128, ROWS / 128), 256, GSMEM_TOTAL>>>(
        attn_h, wout_h, (float*)d_out);
}

// round 16
// speedup vs baseline: 1.6183x; 1.0207x over previous
#include <cuda_runtime.h>
#include <cuda_fp16.h>
#include <cstdint>

#define BATCH   2
#define SEQ     4096
#define DIMM    1024
#define HEADS   16
#define DHEAD   64
#define ROWS    (BATCH*SEQ)
#define DINNER  (HEADS*DHEAD)

__device__ __half g_xn_h[ROWS * DIMM];
__device__ __half g_qh[BATCH * HEADS * SEQ * DHEAD];
__device__ __half g_kh[BATCH * HEADS * SEQ * DHEAD];
__device__ __half g_vh[BATCH * HEADS * SEQ * DHEAD];
__device__ float  g_gate[ROWS * HEADS];
__device__ __half g_attn_h[ROWS * DINNER];
__device__ __half g_wqkv_h[DIMM * 3 * DINNER];   // [K=1024, N=3072] native layout, fp16
__device__ __half g_wout_h[DIMM * DIMM];         // [K=1024, N=1024] native layout, fp16

__device__ __forceinline__ uint32_t smem_u32(const void* p) {
    uint32_t a;
    asm("{ .reg .u64 t; cvta.to.shared.u64 t, %1; cvt.u32.u64 %0, t; }" : "=r"(a) : "l"(p));
    return a;
}
__device__ __forceinline__ void cp16(uint32_t s, const void* g) {
    asm volatile("cp.async.cg.shared.global [%0], [%1], 16;" :: "r"(s), "l"(g));
}
#define CP_COMMIT() asm volatile("cp.async.commit_group;" ::: "memory")
#define CP_WAIT1()  asm volatile("cp.async.wait_group 1;" ::: "memory")
#define CP_WAIT0()  asm volatile("cp.async.wait_group 0;" ::: "memory")

__device__ __forceinline__ void ldsm4(uint32_t& r0, uint32_t& r1, uint32_t& r2, uint32_t& r3, uint32_t a) {
    asm volatile("ldmatrix.sync.aligned.m8n8.x4.shared.b16 {%0,%1,%2,%3}, [%4];"
                 : "=r"(r0), "=r"(r1), "=r"(r2), "=r"(r3) : "r"(a));
}
__device__ __forceinline__ void ldsm4t(uint32_t& r0, uint32_t& r1, uint32_t& r2, uint32_t& r3, uint32_t a) {
    asm volatile("ldmatrix.sync.aligned.m8n8.x4.trans.shared.b16 {%0,%1,%2,%3}, [%4];"
                 : "=r"(r0), "=r"(r1), "=r"(r2), "=r"(r3) : "r"(a));
}
__device__ __forceinline__ void mma16816(float* d, const uint32_t* a, const uint32_t* b) {
    asm volatile("mma.sync.aligned.m16n8k16.row.col.f32.f16.f16.f32 "
                 "{%0,%1,%2,%3}, {%4,%5,%6,%7}, {%8,%9}, {%0,%1,%2,%3};"
                 : "+f"(d[0]), "+f"(d[1]), "+f"(d[2]), "+f"(d[3])
                 : "r"(a[0]), "r"(a[1]), "r"(a[2]), "r"(a[3]), "r"(b[0]), "r"(b[1]));
}
__device__ __forceinline__ uint32_t packh2(float a, float b) {
    __half2 h = __floats2half2_rn(a, b);
    return *(uint32_t*)&h;
}

// RMSNorm -> fp16, fused gates GEMV with coalesced Wg access
__global__ void rms_kernel(const float* __restrict__ x, const float* __restrict__ gamma,
                           const float* __restrict__ Wg, const float* __restrict__ bg) {
    int row = blockIdx.x;
    int t = threadIdx.x;
    __shared__ __half xs[DIMM];
    __shared__ float red[8];
    __shared__ float snorm;
    __shared__ float partial[8][16];
    const float4* xr = (const float4*)(x + (size_t)row * DIMM);
    float4 a = xr[t];
    float ss = a.x*a.x + a.y*a.y + a.z*a.z + a.w*a.w;
    #pragma unroll
    for (int o = 16; o > 0; o >>= 1) ss += __shfl_down_sync(0xffffffffu, ss, o);
    if ((t & 31) == 0) red[t >> 5] = ss;
    __syncthreads();
    if (t == 0) {
        float s = 0.f;
        #pragma unroll
        for (int i = 0; i < 8; i++) s += red[i];
        snorm = 32.0f / fmaxf(sqrtf(s), 1e-12f);
    }
    __syncthreads();
    float sc = snorm;
    float4 g = ((const float4*)gamma)[t];
    __half2 h01 = __floats2half2_rn(a.x * sc * g.x, a.y * sc * g.y);
    __half2 h23 = __floats2half2_rn(a.z * sc * g.z, a.w * sc * g.w);
    __half2* ph = (__half2*)(g_xn_h + (size_t)row * DIMM);
    ph[2*t]   = h01;
    ph[2*t+1] = h23;
    *(__half2*)&xs[4*t]   = h01;
    *(__half2*)&xs[4*t+2] = h23;
    __syncthreads();

    const int h = t & 15;
    const int jbase = t >> 4;
    float sum = 0.f;
    #pragma unroll 8
    for (int p = 0; p < 64; p++) {
        int j = jbase + 16 * p;
        sum += __half2float(xs[j]) * __ldg(&Wg[j * HEADS + h]);
    }
    sum += __shfl_down_sync(0xffffffffu, sum, 16);
    int wrp = t >> 5, lane = t & 31;
    if (lane < 16) partial[wrp][lane] = sum;
    __syncthreads();
    if (t < 16) {
        float s = 0.f;
        #pragma unroll
        for (int wq = 0; wq < 8; wq++) s += partial[wq][t];
        float v = s + bg[t];
        g_gate[row * HEADS + t] = 1.f / (1.f + __expf(-v));
    }
}

// elementwise f32 -> fp16 convert of both weight matrices (native layout)
#define N0Q (DIMM * 3 * DINNER / 4)
#define N1Q (DIMM * DIMM / 4)
__global__ void convert_h(const float* __restrict__ W0, const float* __restrict__ W1) {
    for (int i = blockIdx.x * blockDim.x + threadIdx.x; i < N0Q + N1Q; i += gridDim.x * blockDim.x) {
        if (i < N0Q) {
            float4 v = ((const float4*)W0)[i];
            ((__half2*)g_wqkv_h)[2*i]   = __floats2half2_rn(v.x, v.y);
            ((__half2*)g_wqkv_h)[2*i+1] = __floats2half2_rn(v.z, v.w);
        } else {
            int j = i - N0Q;
            float4 v = ((const float4*)W1)[j];
            ((__half2*)g_wout_h)[2*j]   = __floats2half2_rn(v.x, v.y);
            ((__half2*)g_wout_h)[2*j+1] = __floats2half2_rn(v.z, v.w);
        }
    }
}

// fp16 mma.sync GEMM: 128x128 CTA tile, 4 warps (2x2) of 64x64 each,
// K-block 64, 3-stage cp.async. B in native [K,N] layout via ldmatrix.trans.
#define KBLK        64
#define PITCH_A     144
#define PITCH_B     272
#define MAT_A       (128 * PITCH_A)
#define MAT_B       (64 * PITCH_B)
#define STG_BYTES   (MAT_A + MAT_B)          // 35840
#define NSTAGE      3
#define GSMEM_TOTAL (NSTAGE * STG_BYTES)     // 107520

template<int MODE>
__global__ __launch_bounds__(128, 2) void mma_gemm_kernel(
    const __half* __restrict__ A, const __half* __restrict__ Bw,
    float* __restrict__ C)
{
    constexpr int NB = (MODE == 0) ? 3 * DINNER : DIMM;
    extern __shared__ char smem[];
    const uint32_t sb = smem_u32(smem);
    const int tid = threadIdx.x;
    const int lane = tid & 31, wid = tid >> 5;
    const int wm = wid >> 1, wn = wid & 1;          // 2 x 2 warp grid, 64x64 per warp
    const int bx = blockIdx.x, by = blockIdx.y;

    const __half* gA = A + (size_t)(by * 128) * DIMM;
    const __half* gB = Bw + bx * 128;

    float acc[4][8][4];
    #pragma unroll
    for (int mt = 0; mt < 4; mt++)
        #pragma unroll
        for (int nt = 0; nt < 8; nt++)
            #pragma unroll
            for (int r = 0; r < 4; r++) acc[mt][nt][r] = 0.f;

    const int quad = lane >> 3, l7 = lane & 7;
    const int a_row = (quad & 1) * 8 + l7;
    const int a_ch  = quad >> 1;
    const int t8 = quad, r8 = l7;

    auto load_stage = [&](int kb, int buf) {
        uint32_t s0 = sb + buf * STG_BYTES;
        #pragma unroll
        for (int i = 0; i < 16; i++) {
            int idx = tid + i * 128;                 // 0..2047
            if (idx < 1024) {                        // A: 128 rows x 8 chunks
                int row = idx >> 3, ch = idx & 7;
                cp16(s0 + row * PITCH_A + ch * 16,
                     gA + (size_t)row * DIMM + kb * KBLK + ch * 8);
            } else {                                 // B: 64 rows x 16 chunks
                int j = idx - 1024;
                int row = j >> 4, ch = j & 15;
                cp16(s0 + MAT_A + row * PITCH_B + ch * 16,
                     gB + (size_t)(kb * KBLK + row) * NB + ch * 8);
            }
        }
        CP_COMMIT();
    };

    load_stage(0, 0);
    load_stage(1, 1);

    const int NKB = DIMM / KBLK;                     // 16
    int buf = 0;
    for (int kb = 0; kb < NKB; kb++) {
        CP_WAIT1();
        __syncthreads();
        if (kb + 2 < NKB) {
            int nb = buf + 2; if (nb >= NSTAGE) nb -= NSTAGE;
            load_stage(kb + 2, nb);
        } else {
            CP_COMMIT();
        }
        const uint32_t s0 = sb + buf * STG_BYTES;
        const uint32_t sA = s0, sB = s0 + MAT_A;

        #pragma unroll
        for (int ks = 0; ks < 4; ks++) {
            uint32_t ah[4][4];
            #pragma unroll
            for (int mt = 0; mt < 4; mt++) {
                uint32_t off = (uint32_t)(wm * 64 + mt * 16 + a_row) * PITCH_A + (ks * 2 + a_ch) * 16;
                ldsm4(ah[mt][0], ah[mt][1], ah[mt][2], ah[mt][3], sA + off);
            }
            #pragma unroll
            for (int ng = 0; ng < 4; ng++) {
                uint32_t t0, t1, t2, t3;
                uint32_t off = (uint32_t)(ks * 16 + ((t8 & 1) ? 8 : 0) + r8) * PITCH_B
                             + (wn * 64 + ng * 16) * 2 + ((t8 >= 2) ? 16 : 0);
                ldsm4t(t0, t1, t2, t3, sB + off);
                uint32_t b0[2] = {t0, t1}, b1[2] = {t2, t3};
                #pragma unroll
                for (int mt = 0; mt < 4; mt++) {
                    mma16816(acc[mt][ng * 2 + 0], ah[mt], b0);
                    mma16816(acc[mt][ng * 2 + 1], ah[mt], b1);
                }
            }
        }
        buf++; if (buf >= NSTAGE) buf = 0;
    }

    #pragma unroll
    for (int mt = 0; mt < 4; mt++) {
        #pragma unroll
        for (int nt = 0; nt < 8; nt++) {
            #pragma unroll
            for (int rp = 0; rp < 2; rp++) {
                int row = by * 128 + wm * 64 + mt * 16 + (lane >> 2) + rp * 8;
                int col = bx * 128 + wn * 64 + nt * 8 + (lane & 3) * 2;
                float v0 = acc[mt][nt][rp * 2], v1 = acc[mt][nt][rp * 2 + 1];
                if (MODE == 0) {
                    int which = col >> 10, h = (col >> 6) & 15, d0 = col & 63;
                    int bb = row >> 12, s = row & 4095;
                    __half* base = (which == 0) ? g_qh : (which == 1) ? g_kh : g_vh;
                    if (which == 0) { v0 *= 0.125f; v1 *= 0.125f; }
                    *(__half2*)&base[(((size_t)(bb * HEADS + h)) * SEQ + s) * DHEAD + d0] =
                        __floats2half2_rn(v0, v1);
                } else {
                    *(float2*)&C[(size_t)row * DIMM + col] = make_float2(v0, v1);
                }
            }
        }
    }
}

// tensor-core flash attention: 64-query CTA, 4 warps, double-buffered KV,
// no-max softmax (scores bounded; exp(-1e30)=0 handles masking)
__global__ __launch_bounds__(128) void attn_kernel() {
    const int tile = blockIdx.x, h = blockIdx.y, bb = blockIdx.z;
    const int q0 = tile * 64;
    const int tid = threadIdx.x, w = tid >> 5, l = tid & 31;

    __shared__ __half Qs[64 * 64];
    __shared__ __half KVs[2][2][64 * 64];
    const uint32_t qb = smem_u32(Qs);

    const size_t base = ((size_t)(bb * HEADS + h)) * SEQ * DHEAD;
    const int cstart = (q0 >= 256) ? 0 : ((256 - q0) >> 6);

    #pragma unroll
    for (int i = 0; i < 4; i++) {
        int idx = tid + i * 128;
        int row = idx >> 3, c16 = idx & 7;
        uint32_t bo = row * 128 + c16 * 16;
        cp16(qb + (bo ^ ((bo >> 3) & 0x70)), g_qh + base + (size_t)(q0 + row) * DHEAD + c16 * 8);
    }
    CP_COMMIT();

    {
        const int ks = q0 - 256 + cstart * 64;
        const uint32_t kbb = smem_u32(&KVs[0][0][0]);
        const uint32_t vbb = smem_u32(&KVs[0][1][0]);
        #pragma unroll
        for (int i = 0; i < 4; i++) {
            int idx = tid + i * 128;
            int row = idx >> 3, c16 = idx & 7;
            uint32_t bo = row * 128 + c16 * 16;
            uint32_t sw = bo ^ ((bo >> 3) & 0x70);
            const size_t go = base + (size_t)(ks + row) * DHEAD + c16 * 8;
            cp16(kbb + sw, g_kh + go);
            cp16(vbb + sw, g_vh + go);
        }
        CP_COMMIT();
    }

    CP_WAIT1();
    __syncthreads();
    const int t8 = l >> 3, r8 = l & 7;
    uint32_t qf[4][4];
    #pragma unroll
    for (int kc = 0; kc < 4; kc++) {
        uint32_t bo = (uint32_t)(16 * w + (t8 & 1) * 8 + r8) * 128 + kc * 32 + (t8 >> 1) * 16;
        ldsm4(qf[kc][0], qf[kc][1], qf[kc][2], qf[kc][3], qb + (bo ^ ((bo >> 3) & 0x70)));
    }

    float o[8][4];
    #pragma unroll
    for (int nt = 0; nt < 8; nt++)
        #pragma unroll
        for (int e = 0; e < 4; e++) o[nt][e] = 0.f;
    float l0 = 0.f, l1 = 0.f;
    const int i0 = 16 * w + (l >> 2), i1 = i0 + 8;

    for (int c = cstart; c < 5; c++) {
        const int buf = (c - cstart) & 1;
        const uint32_t kbb = smem_u32(&KVs[buf][0][0]);
        const uint32_t vbb = smem_u32(&KVs[buf][1][0]);

        __syncthreads();
        if (c + 1 < 5) {
            const int ksn = q0 - 256 + (c + 1) * 64;
            const uint32_t kbn = smem_u32(&KVs[buf ^ 1][0][0]);
            const uint32_t vbn = smem_u32(&KVs[buf ^ 1][1][0]);
            #pragma unroll
            for (int i = 0; i < 4; i++) {
                int idx = tid + i * 128;
                int row = idx >> 3, c16 = idx & 7;
                uint32_t bo = row * 128 + c16 * 16;
                uint32_t sw = bo ^ ((bo >> 3) & 0x70);
                const size_t go = base + (size_t)(ksn + row) * DHEAD + c16 * 8;
                cp16(kbn + sw, g_kh + go);
                cp16(vbn + sw, g_vh + go);
            }
            CP_COMMIT();
            CP_WAIT1();
        } else {
            CP_WAIT0();
        }
        __syncthreads();

        float s[8][4];
        #pragma unroll
        for (int nt = 0; nt < 8; nt++)
            #pragma unroll
            for (int e = 0; e < 4; e++) s[nt][e] = 0.f;
        #pragma unroll
        for (int kc = 0; kc < 4; kc++) {
            #pragma unroll
            for (int g = 0; g < 4; g++) {
                uint32_t t0, t1, t2, t3;
                uint32_t bo = (uint32_t)(g * 16 + ((t8 >= 2) ? 8 : 0) + r8) * 128 + kc * 32 + (t8 & 1) * 16;
                ldsm4(t0, t1, t2, t3, kbb + (bo ^ ((bo >> 3) & 0x70)));
                uint32_t b0[2] = {t0, t1}, b1[2] = {t2, t3};
                mma16816(s[2 * g],     qf[kc], b0);
                mma16816(s[2 * g + 1], qf[kc], b1);
            }
        }

        if (c == 0 || c == 4) {
            #pragma unroll
            for (int nt = 0; nt < 8; nt++) {
                #pragma unroll
                for (int e = 0; e < 4; e++) {
                    int j = 8 * nt + 2 * (l & 3) + (e & 1);
                    int i = (e < 2) ? i0 : i1;
                    bool valid = (c == 0) ? (j >= i) : (j <= i);
                    if (!valid) s[nt][e] = -1e30f;
                }
            }
        }

        // no-max softmax: p = exp(s), masked lanes give exp(-1e30) = 0
        #pragma unroll
        for (int nt = 0; nt < 8; nt++) {
            s[nt][0] = __expf(s[nt][0]);
            s[nt][1] = __expf(s[nt][1]);
            s[nt][2] = __expf(s[nt][2]);
            s[nt][3] = __expf(s[nt][3]);
            l0 += s[nt][0] + s[nt][1];
            l1 += s[nt][2] + s[nt][3];
        }

        #pragma unroll
        for (int kc = 0; kc < 4; kc++) {
            uint32_t a[4];
            a[0] = packh2(s[2*kc][0],   s[2*kc][1]);
            a[1] = packh2(s[2*kc][2],   s[2*kc][3]);
            a[2] = packh2(s[2*kc+1][0], s[2*kc+1][1]);
            a[3] = packh2(s[2*kc+1][2], s[2*kc+1][3]);
            #pragma unroll
            for (int ng = 0; ng < 4; ng++) {
                uint32_t t0, t1, t2, t3;
                uint32_t bo = (uint32_t)(kc * 16 + ((t8 & 1) ? 8 : 0) + r8) * 128 + ng * 32 + ((t8 >= 2) ? 16 : 0);
                ldsm4t(t0, t1, t2, t3, vbb + (bo ^ ((bo >> 3) & 0x70)));
                uint32_t b0[2] = {t0, t1}, b1[2] = {t2, t3};
                mma16816(o[2 * ng],     a, b0);
                mma16816(o[2 * ng + 1], a, b1);
            }
        }
    }

    l0 += __shfl_xor_sync(0xffffffffu, l0, 1);
    l0 += __shfl_xor_sync(0xffffffffu, l0, 2);
    l1 += __shfl_xor_sync(0xffffffffu, l1, 1);
    l1 += __shfl_xor_sync(0xffffffffu, l1, 2);

    int rg0 = bb * SEQ + q0 + i0, rg1 = rg0 + 8;
    float inv0 = g_gate[rg0 * HEADS + h] / l0;
    float inv1 = g_gate[rg1 * HEADS + h] / l1;
    #pragma unroll
    for (int nt = 0; nt < 8; nt++) {
        int d = 8 * nt + 2 * (l & 3);
        *(__half2*)&g_attn_h[(size_t)rg0 * DINNER + h * DHEAD + d] =
            __floats2half2_rn(o[nt][0] * inv0, o[nt][1] * inv0);
        *(__half2*)&g_attn_h[(size_t)rg1 * DINNER + h * DHEAD + d] =
            __floats2half2_rn(o[nt][2] * inv1, o[nt][3] * inv1);
    }
}

extern "C" void kernel_launch(void* const* d_in, const int* in_sizes, int n_in,
                              void* d_out, int out_size) {
    const float* x     = (const float*)d_in[0];
    const float* gamma = (const float*)d_in[1];
    const float* Wqkv  = (const float*)d_in[2];
    const float* Wg    = (const float*)d_in[3];
    const float* bg    = (const float*)d_in[4];
    const float* Wout  = (const float*)d_in[5];

    __half *xn_h, *wqkv_h, *wout_h, *attn_h;
    cudaGetSymbolAddress((void**)&xn_h,   g_xn_h);
    cudaGetSymbolAddress((void**)&wqkv_h, g_wqkv_h);
    cudaGetSymbolAddress((void**)&wout_h, g_wout_h);
    cudaGetSymbolAddress((void**)&attn_h, g_attn_h);

    cudaFuncSetAttribute(mma_gemm_kernel<0>, cudaFuncAttributeMaxDynamicSharedMemorySize, GSMEM_TOTAL);
    cudaFuncSetAttribute(mma_gemm_kernel<1>, cudaFuncAttributeMaxDynamicSharedMemorySize, GSMEM_TOTAL);

    convert_h<<<592, 256>>>(Wqkv, Wout);
    rms_kernel<<<ROWS, 256>>>(x, gamma, Wg, bg);
    mma_gemm_kernel<0><<<dim3(3 * DINNER / 128, ROWS / 128), 128, GSMEM_TOTAL>>>(
        xn_h, wqkv_h, nullptr);
    attn_kernel<<<dim3(SEQ / 64, HEADS, BATCH), 128>>>();
    mma_gemm_kernel<1><<<dim3(DIMM / 128, ROWS / 128), 128, GSMEM_TOTAL>>>(
        attn_h, wout_h, (float*)d_out);
}

// round 17
// speedup vs baseline: 1.6730x; 1.0338x over previous
#include <cuda_runtime.h>
#include <cuda_fp16.h>
#include <cstdint>

#define BATCH   2
#define SEQ     4096
#define DIMM    1024
#define HEADS   16
#define DHEAD   64
#define ROWS    (BATCH*SEQ)
#define DINNER  (HEADS*DHEAD)

__device__ __half g_xn_h[ROWS * DIMM];
__device__ __half g_qh[BATCH * HEADS * SEQ * DHEAD];
__device__ __half g_kh[BATCH * HEADS * SEQ * DHEAD];
__device__ __half g_vh[BATCH * HEADS * SEQ * DHEAD];
__device__ float  g_gate[ROWS * HEADS];
__device__ __half g_attn_h[ROWS * DINNER];
__device__ __half g_wqkv_h[DIMM * 3 * DINNER];   // [K=1024, N=3072] native layout, fp16
__device__ __half g_wout_h[DIMM * DIMM];         // [K=1024, N=1024] native layout, fp16

__device__ __forceinline__ uint32_t smem_u32(const void* p) {
    uint32_t a;
    asm("{ .reg .u64 t; cvta.to.shared.u64 t, %1; cvt.u32.u64 %0, t; }" : "=r"(a) : "l"(p));
    return a;
}
__device__ __forceinline__ void cp16(uint32_t s, const void* g) {
    asm volatile("cp.async.cg.shared.global [%0], [%1], 16;" :: "r"(s), "l"(g));
}
#define CP_COMMIT() asm volatile("cp.async.commit_group;" ::: "memory")
#define CP_WAIT1()  asm volatile("cp.async.wait_group 1;" ::: "memory")
#define CP_WAIT0()  asm volatile("cp.async.wait_group 0;" ::: "memory")

__device__ __forceinline__ void ldsm4(uint32_t& r0, uint32_t& r1, uint32_t& r2, uint32_t& r3, uint32_t a) {
    asm volatile("ldmatrix.sync.aligned.m8n8.x4.shared.b16 {%0,%1,%2,%3}, [%4];"
                 : "=r"(r0), "=r"(r1), "=r"(r2), "=r"(r3) : "r"(a));
}
__device__ __forceinline__ void ldsm4t(uint32_t& r0, uint32_t& r1, uint32_t& r2, uint32_t& r3, uint32_t a) {
    asm volatile("ldmatrix.sync.aligned.m8n8.x4.trans.shared.b16 {%0,%1,%2,%3}, [%4];"
                 : "=r"(r0), "=r"(r1), "=r"(r2), "=r"(r3) : "r"(a));
}
__device__ __forceinline__ void mma16816(float* d, const uint32_t* a, const uint32_t* b) {
    asm volatile("mma.sync.aligned.m16n8k16.row.col.f32.f16.f16.f32 "
                 "{%0,%1,%2,%3}, {%4,%5,%6,%7}, {%8,%9}, {%0,%1,%2,%3};"
                 : "+f"(d[0]), "+f"(d[1]), "+f"(d[2]), "+f"(d[3])
                 : "r"(a[0]), "r"(a[1]), "r"(a[2]), "r"(a[3]), "r"(b[0]), "r"(b[1]));
}
__device__ __forceinline__ uint32_t packh2(float a, float b) {
    __half2 h = __floats2half2_rn(a, b);
    return *(uint32_t*)&h;
}

// Fused: blocks [0, ROWS) do RMSNorm + gates; blocks [ROWS, ROWS+592) convert weights.
#define N0Q (DIMM * 3 * DINNER / 4)
#define N1Q (DIMM * DIMM / 4)
#define NCVT 592
__global__ void rms_convert_kernel(const float* __restrict__ x, const float* __restrict__ gamma,
                                   const float* __restrict__ Wg, const float* __restrict__ bg,
                                   const float* __restrict__ W0, const float* __restrict__ W1) {
    if (blockIdx.x >= ROWS) {
        // weight conversion, grid-stride over 592 blocks x 256 threads
        int b = blockIdx.x - ROWS;
        for (int i = b * 256 + threadIdx.x; i < N0Q + N1Q; i += NCVT * 256) {
            if (i < N0Q) {
                float4 v = ((const float4*)W0)[i];
                ((__half2*)g_wqkv_h)[2*i]   = __floats2half2_rn(v.x, v.y);
                ((__half2*)g_wqkv_h)[2*i+1] = __floats2half2_rn(v.z, v.w);
            } else {
                int j = i - N0Q;
                float4 v = ((const float4*)W1)[j];
                ((__half2*)g_wout_h)[2*j]   = __floats2half2_rn(v.x, v.y);
                ((__half2*)g_wout_h)[2*j+1] = __floats2half2_rn(v.z, v.w);
            }
        }
        return;
    }
    int row = blockIdx.x;
    int t = threadIdx.x;
    __shared__ __half xs[DIMM];
    __shared__ float red[8];
    __shared__ float snorm;
    __shared__ float partial[8][16];
    const float4* xr = (const float4*)(x + (size_t)row * DIMM);
    float4 a = xr[t];
    float ss = a.x*a.x + a.y*a.y + a.z*a.z + a.w*a.w;
    #pragma unroll
    for (int o = 16; o > 0; o >>= 1) ss += __shfl_down_sync(0xffffffffu, ss, o);
    if ((t & 31) == 0) red[t >> 5] = ss;
    __syncthreads();
    if (t == 0) {
        float s = 0.f;
        #pragma unroll
        for (int i = 0; i < 8; i++) s += red[i];
        snorm = 32.0f / fmaxf(sqrtf(s), 1e-12f);
    }
    __syncthreads();
    float sc = snorm;
    float4 g = ((const float4*)gamma)[t];
    __half2 h01 = __floats2half2_rn(a.x * sc * g.x, a.y * sc * g.y);
    __half2 h23 = __floats2half2_rn(a.z * sc * g.z, a.w * sc * g.w);
    __half2* ph = (__half2*)(g_xn_h + (size_t)row * DIMM);
    ph[2*t]   = h01;
    ph[2*t+1] = h23;
    *(__half2*)&xs[4*t]   = h01;
    *(__half2*)&xs[4*t+2] = h23;
    __syncthreads();

    const int h = t & 15;
    const int jbase = t >> 4;
    float sum = 0.f;
    #pragma unroll 8
    for (int p = 0; p < 64; p++) {
        int j = jbase + 16 * p;
        sum += __half2float(xs[j]) * __ldg(&Wg[j * HEADS + h]);
    }
    sum += __shfl_down_sync(0xffffffffu, sum, 16);
    int wrp = t >> 5, lane = t & 31;
    if (lane < 16) partial[wrp][lane] = sum;
    __syncthreads();
    if (t < 16) {
        float s = 0.f;
        #pragma unroll
        for (int wq = 0; wq < 8; wq++) s += partial[wq][t];
        float v = s + bg[t];
        g_gate[row * HEADS + t] = 1.f / (1.f + __expf(-v));
    }
}

// fp16 mma.sync GEMM: 128x128 CTA tile, 8 warps (2x4) of 64x32 each,
// K-block 64, 3-stage cp.async. B in native [K,N] layout via ldmatrix.trans.
#define KBLK        64
#define PITCH_A     144
#define PITCH_B     272
#define MAT_A       (128 * PITCH_A)
#define MAT_B       (64 * PITCH_B)
#define STG_BYTES   (MAT_A + MAT_B)          // 35840
#define NSTAGE      3
#define GSMEM_TOTAL (NSTAGE * STG_BYTES)     // 107520

template<int MODE>
__global__ __launch_bounds__(256) void mma_gemm_kernel(
    const __half* __restrict__ A, const __half* __restrict__ Bw,
    float* __restrict__ C)
{
    constexpr int NB = (MODE == 0) ? 3 * DINNER : DIMM;
    extern __shared__ char smem[];
    const uint32_t sb = smem_u32(smem);
    const int tid = threadIdx.x;
    const int lane = tid & 31, wid = tid >> 5;
    const int wm = wid >> 2, wn = wid & 3;
    const int bx = blockIdx.x, by = blockIdx.y;

    const __half* gA = A + (size_t)(by * 128) * DIMM;
    const __half* gB = Bw + bx * 128;

    float acc[4][4][4];
    #pragma unroll
    for (int mt = 0; mt < 4; mt++)
        #pragma unroll
        for (int nt = 0; nt < 4; nt++)
            #pragma unroll
            for (int r = 0; r < 4; r++) acc[mt][nt][r] = 0.f;

    const int quad = lane >> 3, l7 = lane & 7;
    const int a_row = (quad & 1) * 8 + l7;
    const int a_ch  = quad >> 1;
    const int t8 = quad, r8 = l7;

    auto load_stage = [&](int kb, int buf) {
        uint32_t s0 = sb + buf * STG_BYTES;
        #pragma unroll
        for (int i = 0; i < 8; i++) {
            int idx = tid + i * 256;                 // 0..2047
            if (idx < 1024) {                        // A: 128 rows x 8 chunks
                int row = idx >> 3, ch = idx & 7;
                cp16(s0 + row * PITCH_A + ch * 16,
                     gA + (size_t)row * DIMM + kb * KBLK + ch * 8);
            } else {                                 // B: 64 rows x 16 chunks
                int j = idx - 1024;
                int row = j >> 4, ch = j & 15;
                cp16(s0 + MAT_A + row * PITCH_B + ch * 16,
                     gB + (size_t)(kb * KBLK + row) * NB + ch * 8);
            }
        }
        CP_COMMIT();
    };

    load_stage(0, 0);
    load_stage(1, 1);

    const int NKB = DIMM / KBLK;                     // 16
    int buf = 0;
    for (int kb = 0; kb < NKB; kb++) {
        CP_WAIT1();
        __syncthreads();
        if (kb + 2 < NKB) {
            int nb = buf + 2; if (nb >= NSTAGE) nb -= NSTAGE;
            load_stage(kb + 2, nb);
        } else {
            CP_COMMIT();
        }
        const uint32_t s0 = sb + buf * STG_BYTES;
        const uint32_t sA = s0, sB = s0 + MAT_A;

        #pragma unroll
        for (int ks = 0; ks < 4; ks++) {
            uint32_t ah[4][4];
            #pragma unroll
            for (int mt = 0; mt < 4; mt++) {
                uint32_t off = (uint32_t)(wm * 64 + mt * 16 + a_row) * PITCH_A + (ks * 2 + a_ch) * 16;
                ldsm4(ah[mt][0], ah[mt][1], ah[mt][2], ah[mt][3], sA + off);
            }
            #pragma unroll
            for (int np = 0; np < 2; np++) {
                uint32_t t0, t1, t2, t3;
                uint32_t off = (uint32_t)(ks * 16 + ((t8 & 1) ? 8 : 0) + r8) * PITCH_B
                             + (wn * 32 + np * 16) * 2 + ((t8 >= 2) ? 16 : 0);
                ldsm4t(t0, t1, t2, t3, sB + off);
                uint32_t b0[2] = {t0, t1}, b1[2] = {t2, t3};
                #pragma unroll
                for (int mt = 0; mt < 4; mt++) {
                    mma16816(acc[mt][np * 2 + 0], ah[mt], b0);
                    mma16816(acc[mt][np * 2 + 1], ah[mt], b1);
                }
            }
        }
        buf++; if (buf >= NSTAGE) buf = 0;
    }

    #pragma unroll
    for (int mt = 0; mt < 4; mt++) {
        #pragma unroll
        for (int nt = 0; nt < 4; nt++) {
            #pragma unroll
            for (int rp = 0; rp < 2; rp++) {
                int row = by * 128 + wm * 64 + mt * 16 + (lane >> 2) + rp * 8;
                int col = bx * 128 + wn * 32 + nt * 8 + (lane & 3) * 2;
                float v0 = acc[mt][nt][rp * 2], v1 = acc[mt][nt][rp * 2 + 1];
                if (MODE == 0) {
                    int which = col >> 10, h = (col >> 6) & 15, d0 = col & 63;
                    int bb = row >> 12, s = row & 4095;
                    __half* base = (which == 0) ? g_qh : (which == 1) ? g_kh : g_vh;
                    if (which == 0) { v0 *= 0.125f; v1 *= 0.125f; }
                    *(__half2*)&base[(((size_t)(bb * HEADS + h)) * SEQ + s) * DHEAD + d0] =
                        __floats2half2_rn(v0, v1);
                } else {
                    *(float2*)&C[(size_t)row * DIMM + col] = make_float2(v0, v1);
                }
            }
        }
    }
}

// tensor-core flash attention: 64-query CTA, 4 warps, double-buffered KV,
// no-max softmax (scores bounded; exp(-1e30)=0 handles masking)
__global__ __launch_bounds__(128) void attn_kernel() {
    const int tile = blockIdx.x, h = blockIdx.y, bb = blockIdx.z;
    const int q0 = tile * 64;
    const int tid = threadIdx.x, w = tid >> 5, l = tid & 31;

    __shared__ __half Qs[64 * 64];
    __shared__ __half KVs[2][2][64 * 64];
    const uint32_t qb = smem_u32(Qs);

    const size_t base = ((size_t)(bb * HEADS + h)) * SEQ * DHEAD;
    const int cstart = (q0 >= 256) ? 0 : ((256 - q0) >> 6);

    #pragma unroll
    for (int i = 0; i < 4; i++) {
        int idx = tid + i * 128;
        int row = idx >> 3, c16 = idx & 7;
        uint32_t bo = row * 128 + c16 * 16;
        cp16(qb + (bo ^ ((bo >> 3) & 0x70)), g_qh + base + (size_t)(q0 + row) * DHEAD + c16 * 8);
    }
    CP_COMMIT();

    {
        const int ks = q0 - 256 + cstart * 64;
        const uint32_t kbb = smem_u32(&KVs[0][0][0]);
        const uint32_t vbb = smem_u32(&KVs[0][1][0]);
        #pragma unroll
        for (int i = 0; i < 4; i++) {
            int idx = tid + i * 128;
            int row = idx >> 3, c16 = idx & 7;
            uint32_t bo = row * 128 + c16 * 16;
            uint32_t sw = bo ^ ((bo >> 3) & 0x70);
            const size_t go = base + (size_t)(ks + row) * DHEAD + c16 * 8;
            cp16(kbb + sw, g_kh + go);
            cp16(vbb + sw, g_vh + go);
        }
        CP_COMMIT();
    }

    CP_WAIT1();
    __syncthreads();
    const int t8 = l >> 3, r8 = l & 7;
    uint32_t qf[4][4];
    #pragma unroll
    for (int kc = 0; kc < 4; kc++) {
        uint32_t bo = (uint32_t)(16 * w + (t8 & 1) * 8 + r8) * 128 + kc * 32 + (t8 >> 1) * 16;
        ldsm4(qf[kc][0], qf[kc][1], qf[kc][2], qf[kc][3], qb + (bo ^ ((bo >> 3) & 0x70)));
    }

    float o[8][4];
    #pragma unroll
    for (int nt = 0; nt < 8; nt++)
        #pragma unroll
        for (int e = 0; e < 4; e++) o[nt][e] = 0.f;
    float l0 = 0.f, l1 = 0.f;
    const int i0 = 16 * w + (l >> 2), i1 = i0 + 8;

    for (int c = cstart; c < 5; c++) {
        const int buf = (c - cstart) & 1;
        const uint32_t kbb = smem_u32(&KVs[buf][0][0]);
        const uint32_t vbb = smem_u32(&KVs[buf][1][0]);

        __syncthreads();
        if (c + 1 < 5) {
            const int ksn = q0 - 256 + (c + 1) * 64;
            const uint32_t kbn = smem_u32(&KVs[buf ^ 1][0][0]);
            const uint32_t vbn = smem_u32(&KVs[buf ^ 1][1][0]);
            #pragma unroll
            for (int i = 0; i < 4; i++) {
                int idx = tid + i * 128;
                int row = idx >> 3, c16 = idx & 7;
                uint32_t bo = row * 128 + c16 * 16;
                uint32_t sw = bo ^ ((bo >> 3) & 0x70);
                const size_t go = base + (size_t)(ksn + row) * DHEAD + c16 * 8;
                cp16(kbn + sw, g_kh + go);
                cp16(vbn + sw, g_vh + go);
            }
            CP_COMMIT();
            CP_WAIT1();
        } else {
            CP_WAIT0();
        }
        __syncthreads();

        float s[8][4];
        #pragma unroll
        for (int nt = 0; nt < 8; nt++)
            #pragma unroll
            for (int e = 0; e < 4; e++) s[nt][e] = 0.f;
        #pragma unroll
        for (int kc = 0; kc < 4; kc++) {
            #pragma unroll
            for (int g = 0; g < 4; g++) {
                uint32_t t0, t1, t2, t3;
                uint32_t bo = (uint32_t)(g * 16 + ((t8 >= 2) ? 8 : 0) + r8) * 128 + kc * 32 + (t8 & 1) * 16;
                ldsm4(t0, t1, t2, t3, kbb + (bo ^ ((bo >> 3) & 0x70)));
                uint32_t b0[2] = {t0, t1}, b1[2] = {t2, t3};
                mma16816(s[2 * g],     qf[kc], b0);
                mma16816(s[2 * g + 1], qf[kc], b1);
            }
        }

        if (c == 0 || c == 4) {
            #pragma unroll
            for (int nt = 0; nt < 8; nt++) {
                #pragma unroll
                for (int e = 0; e < 4; e++) {
                    int j = 8 * nt + 2 * (l & 3) + (e & 1);
                    int i = (e < 2) ? i0 : i1;
                    bool valid = (c == 0) ? (j >= i) : (j <= i);
                    if (!valid) s[nt][e] = -1e30f;
                }
            }
        }

        #pragma unroll
        for (int nt = 0; nt < 8; nt++) {
            s[nt][0] = __expf(s[nt][0]);
            s[nt][1] = __expf(s[nt][1]);
            s[nt][2] = __expf(s[nt][2]);
            s[nt][3] = __expf(s[nt][3]);
            l0 += s[nt][0] + s[nt][1];
            l1 += s[nt][2] + s[nt][3];
        }

        #pragma unroll
        for (int kc = 0; kc < 4; kc++) {
            uint32_t a[4];
            a[0] = packh2(s[2*kc][0],   s[2*kc][1]);
            a[1] = packh2(s[2*kc][2],   s[2*kc][3]);
            a[2] = packh2(s[2*kc+1][0], s[2*kc+1][1]);
            a[3] = packh2(s[2*kc+1][2], s[2*kc+1][3]);
            #pragma unroll
            for (int ng = 0; ng < 4; ng++) {
                uint32_t t0, t1, t2, t3;
                uint32_t bo = (uint32_t)(kc * 16 + ((t8 & 1) ? 8 : 0) + r8) * 128 + ng * 32 + ((t8 >= 2) ? 16 : 0);
                ldsm4t(t0, t1, t2, t3, vbb + (bo ^ ((bo >> 3) & 0x70)));
                uint32_t b0[2] = {t0, t1}, b1[2] = {t2, t3};
                mma16816(o[2 * ng],     a, b0);
                mma16816(o[2 * ng + 1], a, b1);
            }
        }
    }

    l0 += __shfl_xor_sync(0xffffffffu, l0, 1);
    l0 += __shfl_xor_sync(0xffffffffu, l0, 2);
    l1 += __shfl_xor_sync(0xffffffffu, l1, 1);
    l1 += __shfl_xor_sync(0xffffffffu, l1, 2);

    int rg0 = bb * SEQ + q0 + i0, rg1 = rg0 + 8;
    float inv0 = g_gate[rg0 * HEADS + h] / l0;
    float inv1 = g_gate[rg1 * HEADS + h] / l1;
    #pragma unroll
    for (int nt = 0; nt < 8; nt++) {
        int d = 8 * nt + 2 * (l & 3);
        *(__half2*)&g_attn_h[(size_t)rg0 * DINNER + h * DHEAD + d] =
            __floats2half2_rn(o[nt][0] * inv0, o[nt][1] * inv0);
        *(__half2*)&g_attn_h[(size_t)rg1 * DINNER + h * DHEAD + d] =
            __floats2half2_rn(o[nt][2] * inv1, o[nt][3] * inv1);
    }
}

extern "C" void kernel_launch(void* const* d_in, const int* in_sizes, int n_in,
                              void* d_out, int out_size) {
    const float* x     = (const float*)d_in[0];
    const float* gamma = (const float*)d_in[1];
    const float* Wqkv  = (const float*)d_in[2];
    const float* Wg    = (const float*)d_in[3];
    const float* bg    = (const float*)d_in[4];
    const float* Wout  = (const float*)d_in[5];

    __half *xn_h, *wqkv_h, *wout_h, *attn_h;
    cudaGetSymbolAddress((void**)&xn_h,   g_xn_h);
    cudaGetSymbolAddress((void**)&wqkv_h, g_wqkv_h);
    cudaGetSymbolAddress((void**)&wout_h, g_wout_h);
    cudaGetSymbolAddress((void**)&attn_h, g_attn_h);

    cudaFuncSetAttribute(mma_gemm_kernel<0>, cudaFuncAttributeMaxDynamicSharedMemorySize, GSMEM_TOTAL);
    cudaFuncSetAttribute(mma_gemm_kernel<1>, cudaFuncAttributeMaxDynamicSharedMemorySize, GSMEM_TOTAL);

    rms_convert_kernel<<<ROWS + NCVT, 256>>>(x, gamma, Wg, bg, Wqkv, Wout);
    mma_gemm_kernel<0><<<dim3(3 * DINNER / 128, ROWS / 128), 256, GSMEM_TOTAL>>>(
        xn_h, wqkv_h, nullptr);
    attn_kernel<<<dim3(SEQ / 64, HEADS, BATCH), 128>>>();
    mma_gemm_kernel<1><<<dim3(DIMM / 128, ROWS / 128), 256, GSMEM_TOTAL>>>(
        attn_h, wout_h, (float*)d_out);
}